// round 6
// baseline (speedup 1.0000x reference)
#include <cuda_runtime.h>
#include <cuda_bf16.h>
#include <math.h>

#define NMAX 100000
#define EMAX 1600000
#define H 128
#define C 40
#define SEG 512

typedef unsigned long long ULL;

// ---------------- scratch -------------------------------------------------
__device__ float g_dinv[NMAX];
__device__ int   g_cnt[NMAX];
__device__ int   g_rowstart[NMAX + 1];
__device__ int   g_cursor[NMAX];
__device__ int   g_bsum[(NMAX + SEG - 1) / SEG];
__device__ int2  g_csrp[EMAX];                      // packed {src, w_bits}
__device__ float g_lin[(size_t)NMAX * H];
__device__ __nv_bfloat16 g_linb[(size_t)NMAX * H];  // bf16 shadow of lin
__device__ float g_agg[(size_t)NMAX * H];
__device__ float g_h0 [(size_t)NMAX * H];

// ---------------- f32x2 helpers (classifier) -------------------------------
__device__ __forceinline__ ULL ffma2(ULL a, ULL b, ULL c) {
    ULL d;
    asm("fma.rn.f32x2 %0, %1, %2, %3;" : "=l"(d) : "l"(a), "l"(b), "l"(c));
    return d;
}
__device__ __forceinline__ ULL fdup(float x) {
    ULL r;
    asm("mov.b64 %0, {%1, %1};" : "=l"(r) : "f"(x));
    return r;
}
__device__ __forceinline__ unsigned cvt_tf32(float f) {
    unsigned u;
    asm("cvt.rna.tf32.f32 %0, %1;" : "=r"(u) : "f"(f));
    return u;
}

// ---------------- CSR build ------------------------------------------------
__global__ void k_count(const int* __restrict__ dst, int* cnt, int e) {
    int i = blockIdx.x * blockDim.x + threadIdx.x;
    if (i < e) atomicAdd(&cnt[dst[i]], 1);
}
__global__ void k_dinv(const int* __restrict__ cnt, float* dinv, int n) {
    int i = blockIdx.x * blockDim.x + threadIdx.x;
    if (i < n) dinv[i] = rsqrtf((float)(cnt[i] + 1));
}
__global__ void k_scan1(const int* __restrict__ cnt, int* rowstart, int* bsum, int n) {
    __shared__ int sh[SEG];
    int i = blockIdx.x * SEG + threadIdx.x;
    int v = (i < n) ? cnt[i] : 0;
    sh[threadIdx.x] = v;
    __syncthreads();
#pragma unroll
    for (int o = 1; o < SEG; o <<= 1) {
        int t = (threadIdx.x >= o) ? sh[threadIdx.x - o] : 0;
        __syncthreads();
        sh[threadIdx.x] += t;
        __syncthreads();
    }
    if (i < n) rowstart[i] = sh[threadIdx.x] - v;
    if (threadIdx.x == SEG - 1) bsum[blockIdx.x] = sh[SEG - 1];
}
__global__ void k_scan2(int* bsum, int* rowstart, int nb, int n) {
    __shared__ int sh[256];
    int v = (threadIdx.x < nb) ? bsum[threadIdx.x] : 0;
    sh[threadIdx.x] = v;
    __syncthreads();
#pragma unroll
    for (int o = 1; o < 256; o <<= 1) {
        int t = (threadIdx.x >= o) ? sh[threadIdx.x - o] : 0;
        __syncthreads();
        sh[threadIdx.x] += t;
        __syncthreads();
    }
    if (threadIdx.x < nb) bsum[threadIdx.x] = sh[threadIdx.x] - v;
    if (threadIdx.x == 255) rowstart[n] = sh[255];
}
__global__ void k_scan3(int* rowstart, const int* __restrict__ bsum, int* cursor, int n) {
    int i = blockIdx.x * blockDim.x + threadIdx.x;
    if (i < n) {
        int r = rowstart[i] + bsum[i / SEG];
        rowstart[i] = r;
        cursor[i]   = r;
    }
}
__global__ void k_scatter(const int* __restrict__ src, const int* __restrict__ dst,
                          const float* __restrict__ dinv, int* cursor,
                          int2* csrp, int e) {
    int i = blockIdx.x * blockDim.x + threadIdx.x;
    if (i >= e) return;
    int s = src[i], d = dst[i];
    int p = atomicAdd(&cursor[d], 1);
    float w = dinv[s] * dinv[d];
    csrp[p] = make_int2(s, __float_as_int(w));
}

// ---------------------------------------------------------------------------
// tf32 tensor-core GEMM: C[M,128] = A[M,128] @ B[128,128]
// BM=128 BN=128 BK=32, 256 threads (8 warps, warp tile 32x64), mma.m16n8k8
// smem stride 136 (== 8 mod 32) => conflict-free fragment LDS
// emits fp32 C and bf16 shadow
// ---------------------------------------------------------------------------
__global__ void __launch_bounds__(256)
k_gemm_tf32(const float* __restrict__ A,
            const float* __restrict__ B,
            float* __restrict__ Cm,
            __nv_bfloat16* __restrict__ Cb, int M) {
    __shared__ unsigned AsT[32][136];   // [k][m]
    __shared__ unsigned Bs [32][136];   // [k][n]

    const int tid  = threadIdx.x;
    const int lane = tid & 31;
    const int wid  = tid >> 5;
    const int warp_m = wid & 3;        // 4 warps over M (32 rows each)
    const int warp_n = wid >> 2;       // 2 warps over N (64 cols each)
    const int rowBase = blockIdx.x * 128;

    const int r = lane >> 2;           // groupID
    const int t = lane & 3;            // threadID_in_group

    float acc[2][8][4];
#pragma unroll
    for (int i = 0; i < 2; i++)
#pragma unroll
        for (int j = 0; j < 8; j++)
#pragma unroll
            for (int q = 0; q < 4; q++) acc[i][j][q] = 0.0f;

    for (int k0 = 0; k0 < 128; k0 += 32) {
        // ---- load A tile [128 m][32 k] -> AsT[k][m], tf32-converted
#pragma unroll
        for (int it = 0; it < 4; it++) {
            int idx = tid + it * 256;        // 0..1023
            int m   = idx & 127;
            int kq  = idx >> 7;              // 0..7 (k quad)
            int gr  = rowBase + m;
            float4 v = make_float4(0.f, 0.f, 0.f, 0.f);
            if (gr < M) v = *(const float4*)(A + (size_t)gr * 128 + k0 + kq * 4);
            AsT[kq * 4 + 0][m] = cvt_tf32(v.x);
            AsT[kq * 4 + 1][m] = cvt_tf32(v.y);
            AsT[kq * 4 + 2][m] = cvt_tf32(v.z);
            AsT[kq * 4 + 3][m] = cvt_tf32(v.w);
        }
        // ---- load B tile [32 k][128 n] -> Bs[k][n], tf32-converted
#pragma unroll
        for (int it = 0; it < 4; it++) {
            int idx = tid + it * 256;
            int k   = idx >> 5;              // 0..31
            int n4  = (idx & 31) << 2;
            float4 v = *(const float4*)(B + (size_t)(k0 + k) * 128 + n4);
            uint4 u = make_uint4(cvt_tf32(v.x), cvt_tf32(v.y),
                                 cvt_tf32(v.z), cvt_tf32(v.w));
            *(uint4*)&Bs[k][n4] = u;
        }
        __syncthreads();

#pragma unroll
        for (int ks = 0; ks < 4; ks++) {
            const int kb = ks * 8;
            // A fragments for both m16 tiles
            unsigned a[2][4];
#pragma unroll
            for (int fm = 0; fm < 2; fm++) {
                int mb = warp_m * 32 + fm * 16;
                a[fm][0] = AsT[kb + t    ][mb + r];
                a[fm][1] = AsT[kb + t    ][mb + r + 8];
                a[fm][2] = AsT[kb + t + 4][mb + r];
                a[fm][3] = AsT[kb + t + 4][mb + r + 8];
            }
#pragma unroll
            for (int fn = 0; fn < 8; fn++) {
                int nb = warp_n * 64 + fn * 8;
                unsigned b0 = Bs[kb + t    ][nb + r];
                unsigned b1 = Bs[kb + t + 4][nb + r];
#pragma unroll
                for (int fm = 0; fm < 2; fm++) {
                    asm("mma.sync.aligned.m16n8k8.row.col.f32.tf32.tf32.f32 "
                        "{%0,%1,%2,%3}, {%4,%5,%6,%7}, {%8,%9}, {%0,%1,%2,%3};"
                        : "+f"(acc[fm][fn][0]), "+f"(acc[fm][fn][1]),
                          "+f"(acc[fm][fn][2]), "+f"(acc[fm][fn][3])
                        : "r"(a[fm][0]), "r"(a[fm][1]), "r"(a[fm][2]), "r"(a[fm][3]),
                          "r"(b0), "r"(b1));
                }
            }
        }
        __syncthreads();
    }

    // ---- epilogue: fp32 + bf16 shadow
#pragma unroll
    for (int fm = 0; fm < 2; fm++) {
        int r0 = rowBase + warp_m * 32 + fm * 16 + r;
        int r1 = r0 + 8;
#pragma unroll
        for (int fn = 0; fn < 8; fn++) {
            int col = warp_n * 64 + fn * 8 + 2 * t;
            if (r0 < M) {
                *(float2*)(Cm + (size_t)r0 * 128 + col) =
                    make_float2(acc[fm][fn][0], acc[fm][fn][1]);
                *(__nv_bfloat162*)(Cb + (size_t)r0 * 128 + col) =
                    __float22bfloat162_rn(make_float2(acc[fm][fn][0], acc[fm][fn][1]));
            }
            if (r1 < M) {
                *(float2*)(Cm + (size_t)r1 * 128 + col) =
                    make_float2(acc[fm][fn][2], acc[fm][fn][3]);
                *(__nv_bfloat162*)(Cb + (size_t)r1 * 128 + col) =
                    __float22bfloat162_rn(make_float2(acc[fm][fn][2], acc[fm][fn][3]));
            }
        }
    }
}

// ---------------------------------------------------------------------------
// fused gather: warp per dst node, 8-deep feature pipeline + idx prefetch
// ---------------------------------------------------------------------------
__device__ __forceinline__ void acc_bf16(float4& acc, float w, ULL packed) {
    __nv_bfloat162 lo = *(__nv_bfloat162*)&packed;
    __nv_bfloat162 hi = *((__nv_bfloat162*)&packed + 1);
    float2 f0 = __bfloat1622float2(lo);
    float2 f1 = __bfloat1622float2(hi);
    acc.x = fmaf(w, f0.x, acc.x);
    acc.y = fmaf(w, f0.y, acc.y);
    acc.z = fmaf(w, f1.x, acc.z);
    acc.w = fmaf(w, f1.y, acc.w);
}

__global__ void k_gather(const float* __restrict__ lin,
                         const __nv_bfloat16* __restrict__ linb,
                         const float* __restrict__ dinv,
                         const int* __restrict__ rowstart,
                         const int2* __restrict__ csrp,
                         const float* __restrict__ bias,
                         const float* __restrict__ res,
                         float* __restrict__ out, int n) {
    int v = (blockIdx.x * blockDim.x + threadIdx.x) >> 5;
    int lane = threadIdx.x & 31;
    if (v >= n) return;

    int beg = rowstart[v];
    int end = rowstart[v + 1];
    float dv = dinv[v];
    float sl = dv * dv;
    const size_t lo = (size_t)(lane << 2);

    float4 acc = *(const float4*)(lin + (size_t)v * 128 + lo);
    acc.x *= sl; acc.y *= sl; acc.z *= sl; acc.w *= sl;

    int i = beg;
    int cnt8 = (end - beg) >> 3;

    if (cnt8 > 0) {
        int2 p[8];
#pragma unroll
        for (int j = 0; j < 8; j++) p[j] = csrp[i + j];

        for (int b = 0; b < cnt8; b++) {
            // 8 feature loads in flight
            ULL f[8];
#pragma unroll
            for (int j = 0; j < 8; j++)
                f[j] = *(const ULL*)(linb + (size_t)p[j].x * 128 + lo);
            // prefetch next 8 index pairs while features are in flight
            bool more = (b + 1 < cnt8);
            int2 q[8];
            if (more) {
#pragma unroll
                for (int j = 0; j < 8; j++) q[j] = csrp[i + 8 + j];
            }
            // accumulate
#pragma unroll
            for (int j = 0; j < 8; j++)
                acc_bf16(acc, __int_as_float(p[j].y), f[j]);
            if (more) {
#pragma unroll
                for (int j = 0; j < 8; j++) p[j] = q[j];
            }
            i += 8;
        }
    }
    for (; i < end; i++) {
        int2 pp = csrp[i];
        ULL f = *(const ULL*)(linb + (size_t)pp.x * 128 + lo);
        acc_bf16(acc, __int_as_float(pp.y), f);
    }

    float4 bb = ((const float4*)bias)[lane];
    acc.x = fmaxf(acc.x + bb.x, 0.f);
    acc.y = fmaxf(acc.y + bb.y, 0.f);
    acc.z = fmaxf(acc.z + bb.z, 0.f);
    acc.w = fmaxf(acc.w + bb.w, 0.f);
    if (res) {
        float4 rr = *(const float4*)(res + (size_t)v * 128 + lo);
        acc.x += rr.x; acc.y += rr.y; acc.z += rr.z; acc.w += rr.w;
    }
    *(float4*)(out + (size_t)v * 128 + lo) = acc;
}

// ---------------------------------------------------------------------------
// classifier GEMM + fused log_softmax (packed f32x2)
// ---------------------------------------------------------------------------
__global__ void k_cls_gemm(const float* __restrict__ h,
                           const float* __restrict__ wl,
                           const float* __restrict__ bl,
                           float* __restrict__ out, int n) {
    __shared__ float AsT[16][258];
    __shared__ float Bsf[16 * C];
    __shared__ float sbl[C];

    const int tx = threadIdx.x & 7;
    const int ty = threadIdx.x >> 3;
    const int rowBase = blockIdx.x * 256;

    if (threadIdx.x < C) sbl[threadIdx.x] = bl[threadIdx.x];

    ULL acc[4][5];
#pragma unroll
    for (int i = 0; i < 4; i++)
#pragma unroll
        for (int j = 0; j < 5; j++) acc[i][j] = 0ull;

    const int gr = rowBase + threadIdx.x;

    for (int k0 = 0; k0 < 128; k0 += 16) {
#pragma unroll
        for (int i = 0; i < 4; i++) {
            float4 v = make_float4(0.f, 0.f, 0.f, 0.f);
            if (gr < n) v = *(const float4*)(h + (size_t)gr * 128 + k0 + i * 4);
            AsT[i * 4 + 0][threadIdx.x] = v.x;
            AsT[i * 4 + 1][threadIdx.x] = v.y;
            AsT[i * 4 + 2][threadIdx.x] = v.z;
            AsT[i * 4 + 3][threadIdx.x] = v.w;
        }
        for (int i = threadIdx.x; i < 16 * C; i += 256)
            Bsf[i] = wl[k0 * C + i];
        __syncthreads();

#pragma unroll 4
        for (int kk = 0; kk < 16; kk++) {
            ULL a0 = *(const ULL*)&AsT[kk][ty * 8 + 0];
            ULL a1 = *(const ULL*)&AsT[kk][ty * 8 + 2];
            ULL a2 = *(const ULL*)&AsT[kk][ty * 8 + 4];
            ULL a3 = *(const ULL*)&AsT[kk][ty * 8 + 6];
            const float* bp = &Bsf[kk * C + tx * 5];
            ULL b0 = fdup(bp[0]), b1 = fdup(bp[1]), b2 = fdup(bp[2]);
            ULL b3 = fdup(bp[3]), b4 = fdup(bp[4]);
#define CLS_ROW(i, ai) \
            acc[i][0] = ffma2(ai, b0, acc[i][0]); \
            acc[i][1] = ffma2(ai, b1, acc[i][1]); \
            acc[i][2] = ffma2(ai, b2, acc[i][2]); \
            acc[i][3] = ffma2(ai, b3, acc[i][3]); \
            acc[i][4] = ffma2(ai, b4, acc[i][4]);
            CLS_ROW(0, a0) CLS_ROW(1, a1) CLS_ROW(2, a2) CLS_ROW(3, a3)
#undef CLS_ROW
        }
        __syncthreads();
    }

    const float bb0 = sbl[tx * 5 + 0], bb1 = sbl[tx * 5 + 1], bb2 = sbl[tx * 5 + 2];
    const float bb3 = sbl[tx * 5 + 3], bb4 = sbl[tx * 5 + 4];

#pragma unroll
    for (int i = 0; i < 4; i++) {
#pragma unroll
        for (int half = 0; half < 2; half++) {
            int r0 = rowBase + ty * 8 + 2 * i + half;
            float2 q0 = *(float2*)&acc[i][0];
            float2 q1 = *(float2*)&acc[i][1];
            float2 q2 = *(float2*)&acc[i][2];
            float2 q3 = *(float2*)&acc[i][3];
            float2 q4 = *(float2*)&acc[i][4];
            float l0 = (half ? q0.y : q0.x) + bb0;
            float l1 = (half ? q1.y : q1.x) + bb1;
            float l2 = (half ? q2.y : q2.x) + bb2;
            float l3 = (half ? q3.y : q3.x) + bb3;
            float l4 = (half ? q4.y : q4.x) + bb4;

            float m = fmaxf(fmaxf(fmaxf(l0, l1), fmaxf(l2, l3)), l4);
            m = fmaxf(m, __shfl_xor_sync(0xffffffffu, m, 1));
            m = fmaxf(m, __shfl_xor_sync(0xffffffffu, m, 2));
            m = fmaxf(m, __shfl_xor_sync(0xffffffffu, m, 4));
            float se = __expf(l0 - m) + __expf(l1 - m) + __expf(l2 - m)
                     + __expf(l3 - m) + __expf(l4 - m);
            se += __shfl_xor_sync(0xffffffffu, se, 1);
            se += __shfl_xor_sync(0xffffffffu, se, 2);
            se += __shfl_xor_sync(0xffffffffu, se, 4);
            float lse = __logf(se) + m;

            if (r0 < n) {
                float* op = out + (size_t)r0 * C + tx * 5;
                op[0] = l0 - lse; op[1] = l1 - lse; op[2] = l2 - lse;
                op[3] = l3 - lse; op[4] = l4 - lse;
            }
        }
    }
}

// ---------------------------------------------------------------------------
// launch
// ---------------------------------------------------------------------------
extern "C" void kernel_launch(void* const* d_in, const int* in_sizes, int n_in,
                              void* d_out, int out_size) {
    const float* x   = (const float*)d_in[0];
    const int*   ei  = (const int*)d_in[1];
    const float* w0  = (const float*)d_in[2];
    const float* b0  = (const float*)d_in[3];
    const float* w1  = (const float*)d_in[4];
    const float* b1  = (const float*)d_in[5];
    const float* wl  = (const float*)d_in[6];
    const float* bl  = (const float*)d_in[7];
    float* out = (float*)d_out;

    const int n = in_sizes[0] / H;
    const int e = in_sizes[1] / 2;
    const int* src = ei;
    const int* dst = ei + e;

    float *dinv, *lin, *agg, *h0;
    __nv_bfloat16* linb;
    int *cnt, *rowstart, *cursor, *bsum;
    int2* csrp;
    cudaGetSymbolAddress((void**)&dinv,     g_dinv);
    cudaGetSymbolAddress((void**)&cnt,      g_cnt);
    cudaGetSymbolAddress((void**)&rowstart, g_rowstart);
    cudaGetSymbolAddress((void**)&cursor,   g_cursor);
    cudaGetSymbolAddress((void**)&bsum,     g_bsum);
    cudaGetSymbolAddress((void**)&csrp,     g_csrp);
    cudaGetSymbolAddress((void**)&lin,      g_lin);
    cudaGetSymbolAddress((void**)&linb,     g_linb);
    cudaGetSymbolAddress((void**)&agg,      g_agg);
    cudaGetSymbolAddress((void**)&h0,       g_h0);

    static cudaStream_t s2 = nullptr;
    static cudaEvent_t evFork = nullptr, evJoin = nullptr;
    if (!s2) {
        cudaStreamCreateWithFlags(&s2, cudaStreamNonBlocking);
        cudaEventCreateWithFlags(&evFork, cudaEventDisableTiming);
        cudaEventCreateWithFlags(&evJoin, cudaEventDisableTiming);
    }

    const int TB = 256;
    const int nb = (n + SEG - 1) / SEG;
    const int gemmBlocks   = (n + 127) / 128;
    const int gatherBlocks = (n * 32 + TB - 1) / TB;

    // fork: CSR build on s2, GEMM0 on main stream
    cudaEventRecord(evFork, 0);
    cudaStreamWaitEvent(s2, evFork, 0);

    cudaMemsetAsync(cnt, 0, n * sizeof(int), s2);
    k_count  <<<(e + TB - 1) / TB, TB, 0, s2>>>(dst, cnt, e);
    k_dinv   <<<(n + TB - 1) / TB, TB, 0, s2>>>(cnt, dinv, n);
    k_scan1  <<<nb, SEG, 0, s2>>>(cnt, rowstart, bsum, n);
    k_scan2  <<<1, 256, 0, s2>>>(bsum, rowstart, nb, n);
    k_scan3  <<<(n + TB - 1) / TB, TB, 0, s2>>>(rowstart, bsum, cursor, n);
    k_scatter<<<(e + TB - 1) / TB, TB, 0, s2>>>(src, dst, dinv, cursor, csrp, e);
    cudaEventRecord(evJoin, s2);

    k_gemm_tf32<<<gemmBlocks, TB>>>(x, w0, lin, linb, n);

    cudaStreamWaitEvent(0, evJoin, 0);

    k_gather <<<gatherBlocks, TB>>>(lin, linb, dinv, rowstart, csrp,
                                    b0, nullptr, h0, n);
    k_gemm_tf32<<<gemmBlocks, TB>>>(h0, w1, lin, linb, n);
    k_gather <<<gatherBlocks, TB>>>(lin, linb, dinv, rowstart, csrp,
                                    b1, h0, agg, n);
    k_cls_gemm<<<(n + 255) / 256, TB>>>(agg, wl, bl, out, n);
}

// round 9
// speedup vs baseline: 1.0897x; 1.0897x over previous
#include <cuda_runtime.h>
#include <cuda_bf16.h>
#include <math.h>

#define NMAX 100000
#define EMAX 1600000
#define H 128
#define C 40
#define SEG 512

typedef unsigned long long ULL;

// ---------------- scratch -------------------------------------------------
__device__ float g_dinv[NMAX];
__device__ int   g_cnt[NMAX];
__device__ int   g_rowstart[NMAX + 1];
__device__ int   g_cursor[NMAX];
__device__ int   g_bsum[(NMAX + SEG - 1) / SEG];
__device__ int   g_csr_src[EMAX];
__device__ float g_csr_w[EMAX];
__device__ float g_lin[(size_t)NMAX * H];
__device__ __nv_bfloat16 g_linb[(size_t)NMAX * H];   // bf16 shadow of lin
__device__ float g_agg[(size_t)NMAX * H];
__device__ float g_h0 [(size_t)NMAX * H];

// ---------------- f32x2 + cache-policy helpers ------------------------------
__device__ __forceinline__ ULL ffma2(ULL a, ULL b, ULL c) {
    ULL d;
    asm("fma.rn.f32x2 %0, %1, %2, %3;" : "=l"(d) : "l"(a), "l"(b), "l"(c));
    return d;
}
__device__ __forceinline__ ULL fdup(float x) {
    ULL r;
    asm("mov.b64 %0, {%1, %1};" : "=l"(r) : "f"(x));
    return r;
}
__device__ __forceinline__ ULL policy_evict_last() {
    ULL pol;
    asm("createpolicy.fractional.L2::evict_last.b64 %0, 1.0;" : "=l"(pol));
    return pol;
}
__device__ __forceinline__ ULL policy_evict_first() {
    ULL pol;
    asm("createpolicy.fractional.L2::evict_first.b64 %0, 1.0;" : "=l"(pol));
    return pol;
}
// linb: keep resident in L2
__device__ __forceinline__ ULL ld_linb(const void* p, ULL pol) {
    ULL v;
    asm("ld.global.nc.L2::cache_hint.b64 %0, [%1], %2;"
        : "=l"(v) : "l"(p), "l"(pol));
    return v;
}
__device__ __forceinline__ void st_linb(void* p, ULL v, ULL pol) {
    asm volatile("st.global.L2::cache_hint.b64 [%0], %1, %2;"
                 :: "l"(p), "l"(v), "l"(pol) : "memory");
}
// streaming fp32 arrays: do not pollute L2
__device__ __forceinline__ float4 ld_stream_f4(const void* p, ULL pol) {
    float4 v;
    asm("ld.global.nc.L2::cache_hint.v4.f32 {%0,%1,%2,%3}, [%4], %5;"
        : "=f"(v.x), "=f"(v.y), "=f"(v.z), "=f"(v.w) : "l"(p), "l"(pol));
    return v;
}
__device__ __forceinline__ void st_stream_f4(void* p, float4 v, ULL pol) {
    asm volatile("st.global.L2::cache_hint.v4.f32 [%0], {%1,%2,%3,%4}, %5;"
                 :: "l"(p), "f"(v.x), "f"(v.y), "f"(v.z), "f"(v.w), "l"(pol)
                 : "memory");
}

// ---------------- CSR build ------------------------------------------------
__global__ void k_count(const int* __restrict__ dst, int* cnt, int e) {
    int i = blockIdx.x * blockDim.x + threadIdx.x;
    if (i < e) atomicAdd(&cnt[dst[i]], 1);
}
__global__ void k_dinv(const int* __restrict__ cnt, float* dinv, int n) {
    int i = blockIdx.x * blockDim.x + threadIdx.x;
    if (i < n) dinv[i] = rsqrtf((float)(cnt[i] + 1));
}
__global__ void k_scan1(const int* __restrict__ cnt, int* rowstart, int* bsum, int n) {
    __shared__ int sh[SEG];
    int i = blockIdx.x * SEG + threadIdx.x;
    int v = (i < n) ? cnt[i] : 0;
    sh[threadIdx.x] = v;
    __syncthreads();
#pragma unroll
    for (int o = 1; o < SEG; o <<= 1) {
        int t = (threadIdx.x >= o) ? sh[threadIdx.x - o] : 0;
        __syncthreads();
        sh[threadIdx.x] += t;
        __syncthreads();
    }
    if (i < n) rowstart[i] = sh[threadIdx.x] - v;
    if (threadIdx.x == SEG - 1) bsum[blockIdx.x] = sh[SEG - 1];
}
__global__ void k_scan2(int* bsum, int* rowstart, int nb, int n) {
    __shared__ int sh[256];
    int v = (threadIdx.x < nb) ? bsum[threadIdx.x] : 0;
    sh[threadIdx.x] = v;
    __syncthreads();
#pragma unroll
    for (int o = 1; o < 256; o <<= 1) {
        int t = (threadIdx.x >= o) ? sh[threadIdx.x - o] : 0;
        __syncthreads();
        sh[threadIdx.x] += t;
        __syncthreads();
    }
    if (threadIdx.x < nb) bsum[threadIdx.x] = sh[threadIdx.x] - v;
    if (threadIdx.x == 255) rowstart[n] = sh[255];
}
__global__ void k_scan3(int* rowstart, const int* __restrict__ bsum, int* cursor, int n) {
    int i = blockIdx.x * blockDim.x + threadIdx.x;
    if (i < n) {
        int r = rowstart[i] + bsum[i / SEG];
        rowstart[i] = r;
        cursor[i]   = r;
    }
}
__global__ void k_scatter(const int* __restrict__ src, const int* __restrict__ dst,
                          const float* __restrict__ dinv, int* cursor,
                          int* csr_src, float* csr_w, int e) {
    int i = blockIdx.x * blockDim.x + threadIdx.x;
    if (i >= e) return;
    int s = src[i], d = dst[i];
    int p = atomicAdd(&cursor[d], 1);
    csr_src[p] = s;
    csr_w[p]   = dinv[s] * dinv[d];
}

// ---------------------------------------------------------------------------
// GEMM: C[M,128] = A[M,128] @ B[128,128]  (fp32, packed f32x2 FMA)
// emits fp32 C (evict_first) and bf16 shadow (evict_last)
// ---------------------------------------------------------------------------
__global__ void k_gemm128(const float* __restrict__ A,
                          const float* __restrict__ B,
                          float* __restrict__ Cm,
                          __nv_bfloat16* __restrict__ Cb, int M) {
    __shared__ float AsT[32][66];
    __shared__ float Bs[32][128];

    const int tx = threadIdx.x & 31;
    const int ty = threadIdx.x >> 5;
    const int rowBase = blockIdx.x * 64;

    ULL acc[4][4];
#pragma unroll
    for (int i = 0; i < 4; i++)
#pragma unroll
        for (int j = 0; j < 4; j++) acc[i][j] = 0ull;

    const int r  = threadIdx.x >> 2;
    const int c4 = (threadIdx.x & 3) << 2;
    const int gr = rowBase + r;

    for (int k0 = 0; k0 < 128; k0 += 32) {
#pragma unroll
        for (int hh = 0; hh < 2; hh++) {
            int c = c4 + hh * 16;
            float4 v = make_float4(0.f, 0.f, 0.f, 0.f);
            if (gr < M) v = *(const float4*)(A + (size_t)gr * 128 + k0 + c);
            AsT[c + 0][r] = v.x; AsT[c + 1][r] = v.y;
            AsT[c + 2][r] = v.z; AsT[c + 3][r] = v.w;
        }
#pragma unroll
        for (int it = 0; it < 4; it++) {
            int idx = threadIdx.x + it * 256;
            int rr  = idx >> 5;
            int cc  = (idx & 31) << 2;
            *(float4*)&Bs[rr][cc] = *(const float4*)(B + (size_t)(k0 + rr) * 128 + cc);
        }
        __syncthreads();

#pragma unroll 8
        for (int kk = 0; kk < 32; kk++) {
            ULL a0 = *(const ULL*)&AsT[kk][ty * 8 + 0];
            ULL a1 = *(const ULL*)&AsT[kk][ty * 8 + 2];
            ULL a2 = *(const ULL*)&AsT[kk][ty * 8 + 4];
            ULL a3 = *(const ULL*)&AsT[kk][ty * 8 + 6];
            float4 bq = *(const float4*)&Bs[kk][tx << 2];
            ULL b0 = fdup(bq.x), b1 = fdup(bq.y), b2 = fdup(bq.z), b3 = fdup(bq.w);
            acc[0][0] = ffma2(a0, b0, acc[0][0]);
            acc[0][1] = ffma2(a0, b1, acc[0][1]);
            acc[0][2] = ffma2(a0, b2, acc[0][2]);
            acc[0][3] = ffma2(a0, b3, acc[0][3]);
            acc[1][0] = ffma2(a1, b0, acc[1][0]);
            acc[1][1] = ffma2(a1, b1, acc[1][1]);
            acc[1][2] = ffma2(a1, b2, acc[1][2]);
            acc[1][3] = ffma2(a1, b3, acc[1][3]);
            acc[2][0] = ffma2(a2, b0, acc[2][0]);
            acc[2][1] = ffma2(a2, b1, acc[2][1]);
            acc[2][2] = ffma2(a2, b2, acc[2][2]);
            acc[2][3] = ffma2(a2, b3, acc[2][3]);
            acc[3][0] = ffma2(a3, b0, acc[3][0]);
            acc[3][1] = ffma2(a3, b1, acc[3][1]);
            acc[3][2] = ffma2(a3, b2, acc[3][2]);
            acc[3][3] = ffma2(a3, b3, acc[3][3]);
        }
        __syncthreads();
    }

    const ULL polLast  = policy_evict_last();
    const ULL polFirst = policy_evict_first();

#pragma unroll
    for (int i = 0; i < 4; i++) {
        float2 p0 = *(float2*)&acc[i][0];
        float2 p1 = *(float2*)&acc[i][1];
        float2 p2 = *(float2*)&acc[i][2];
        float2 p3 = *(float2*)&acc[i][3];
        int r0 = rowBase + ty * 8 + 2 * i;
        if (r0 < M) {
            float4 v = make_float4(p0.x, p1.x, p2.x, p3.x);
            st_stream_f4(Cm + (size_t)r0 * 128 + (tx << 2), v, polFirst);
            __nv_bfloat162 h0 = __float22bfloat162_rn(make_float2(v.x, v.y));
            __nv_bfloat162 h1 = __float22bfloat162_rn(make_float2(v.z, v.w));
            ULL packed = ((ULL)*(unsigned*)&h1 << 32) | *(unsigned*)&h0;
            st_linb(Cb + (size_t)r0 * 128 + (tx << 2), packed, polLast);
        }
        if (r0 + 1 < M) {
            float4 v = make_float4(p0.y, p1.y, p2.y, p3.y);
            st_stream_f4(Cm + (size_t)(r0 + 1) * 128 + (tx << 2), v, polFirst);
            __nv_bfloat162 h0 = __float22bfloat162_rn(make_float2(v.x, v.y));
            __nv_bfloat162 h1 = __float22bfloat162_rn(make_float2(v.z, v.w));
            ULL packed = ((ULL)*(unsigned*)&h1 << 32) | *(unsigned*)&h0;
            st_linb(Cb + (size_t)(r0 + 1) * 128 + (tx << 2), packed, polLast);
        }
    }
}

// ---------------------------------------------------------------------------
// fused gather (warp per dst node, unroll 4):
//   neighbor bf16 reads pinned in L2 (evict_last); streams bypass (evict_first)
// ---------------------------------------------------------------------------
__device__ __forceinline__ void acc_bf16(float4& acc, float w, ULL packed) {
    __nv_bfloat162 lo = *(__nv_bfloat162*)&packed;
    __nv_bfloat162 hi = *((__nv_bfloat162*)&packed + 1);
    float2 f0 = __bfloat1622float2(lo);
    float2 f1 = __bfloat1622float2(hi);
    acc.x = fmaf(w, f0.x, acc.x);
    acc.y = fmaf(w, f0.y, acc.y);
    acc.z = fmaf(w, f1.x, acc.z);
    acc.w = fmaf(w, f1.y, acc.w);
}

__global__ void k_gather(const float* __restrict__ lin,
                         const __nv_bfloat16* __restrict__ linb,
                         const float* __restrict__ dinv,
                         const int* __restrict__ rowstart,
                         const int* __restrict__ csr_src,
                         const float* __restrict__ csr_w,
                         const float* __restrict__ bias,
                         const float* __restrict__ res,
                         float* __restrict__ out, int n) {
    int v = (blockIdx.x * blockDim.x + threadIdx.x) >> 5;
    int lane = threadIdx.x & 31;
    if (v >= n) return;

    const ULL polLast  = policy_evict_last();
    const ULL polFirst = policy_evict_first();

    int beg = rowstart[v];
    int end = rowstart[v + 1];
    float dv = dinv[v];
    float sl = dv * dv;
    const size_t lo = (size_t)(lane << 2);

    float4 acc = ld_stream_f4(lin + (size_t)v * 128 + lo, polFirst);
    acc.x *= sl; acc.y *= sl; acc.z *= sl; acc.w *= sl;

    int i = beg;
    for (; i + 3 < end; i += 4) {
        int   s0 = csr_src[i],     s1 = csr_src[i + 1];
        int   s2 = csr_src[i + 2], s3 = csr_src[i + 3];
        float w0 = csr_w[i],       w1 = csr_w[i + 1];
        float w2 = csr_w[i + 2],   w3 = csr_w[i + 3];
        ULL x0 = ld_linb(linb + (size_t)s0 * 128 + lo, polLast);
        ULL x1 = ld_linb(linb + (size_t)s1 * 128 + lo, polLast);
        ULL x2 = ld_linb(linb + (size_t)s2 * 128 + lo, polLast);
        ULL x3 = ld_linb(linb + (size_t)s3 * 128 + lo, polLast);
        acc_bf16(acc, w0, x0);
        acc_bf16(acc, w1, x1);
        acc_bf16(acc, w2, x2);
        acc_bf16(acc, w3, x3);
    }
    for (; i < end; i++) {
        int   s0 = csr_src[i];
        float w0 = csr_w[i];
        ULL x0 = ld_linb(linb + (size_t)s0 * 128 + lo, polLast);
        acc_bf16(acc, w0, x0);
    }

    float4 bb = ((const float4*)bias)[lane];
    acc.x = fmaxf(acc.x + bb.x, 0.f);
    acc.y = fmaxf(acc.y + bb.y, 0.f);
    acc.z = fmaxf(acc.z + bb.z, 0.f);
    acc.w = fmaxf(acc.w + bb.w, 0.f);
    if (res) {
        float4 rr = ld_stream_f4(res + (size_t)v * 128 + lo, polFirst);
        acc.x += rr.x; acc.y += rr.y; acc.z += rr.z; acc.w += rr.w;
    }
    st_stream_f4(out + (size_t)v * 128 + lo, acc, polFirst);
}

// ---------------------------------------------------------------------------
// classifier GEMM + fused log_softmax (packed f32x2)
// ---------------------------------------------------------------------------
__global__ void k_cls_gemm(const float* __restrict__ h,
                           const float* __restrict__ wl,
                           const float* __restrict__ bl,
                           float* __restrict__ out, int n) {
    __shared__ float AsT[16][258];
    __shared__ float Bsf[16 * C];
    __shared__ float sbl[C];

    const int tx = threadIdx.x & 7;
    const int ty = threadIdx.x >> 3;
    const int rowBase = blockIdx.x * 256;

    if (threadIdx.x < C) sbl[threadIdx.x] = bl[threadIdx.x];

    ULL acc[4][5];
#pragma unroll
    for (int i = 0; i < 4; i++)
#pragma unroll
        for (int j = 0; j < 5; j++) acc[i][j] = 0ull;

    const int gr = rowBase + threadIdx.x;

    for (int k0 = 0; k0 < 128; k0 += 16) {
#pragma unroll
        for (int i = 0; i < 4; i++) {
            float4 v = make_float4(0.f, 0.f, 0.f, 0.f);
            if (gr < n) v = *(const float4*)(h + (size_t)gr * 128 + k0 + i * 4);
            AsT[i * 4 + 0][threadIdx.x] = v.x;
            AsT[i * 4 + 1][threadIdx.x] = v.y;
            AsT[i * 4 + 2][threadIdx.x] = v.z;
            AsT[i * 4 + 3][threadIdx.x] = v.w;
        }
        for (int i = threadIdx.x; i < 16 * C; i += 256)
            Bsf[i] = wl[k0 * C + i];
        __syncthreads();

#pragma unroll 4
        for (int kk = 0; kk < 16; kk++) {
            ULL a0 = *(const ULL*)&AsT[kk][ty * 8 + 0];
            ULL a1 = *(const ULL*)&AsT[kk][ty * 8 + 2];
            ULL a2 = *(const ULL*)&AsT[kk][ty * 8 + 4];
            ULL a3 = *(const ULL*)&AsT[kk][ty * 8 + 6];
            const float* bp = &Bsf[kk * C + tx * 5];
            ULL b0 = fdup(bp[0]), b1 = fdup(bp[1]), b2 = fdup(bp[2]);
            ULL b3 = fdup(bp[3]), b4 = fdup(bp[4]);
#define CLS_ROW(i, ai) \
            acc[i][0] = ffma2(ai, b0, acc[i][0]); \
            acc[i][1] = ffma2(ai, b1, acc[i][1]); \
            acc[i][2] = ffma2(ai, b2, acc[i][2]); \
            acc[i][3] = ffma2(ai, b3, acc[i][3]); \
            acc[i][4] = ffma2(ai, b4, acc[i][4]);
            CLS_ROW(0, a0) CLS_ROW(1, a1) CLS_ROW(2, a2) CLS_ROW(3, a3)
#undef CLS_ROW
        }
        __syncthreads();
    }

    const float bb0 = sbl[tx * 5 + 0], bb1 = sbl[tx * 5 + 1], bb2 = sbl[tx * 5 + 2];
    const float bb3 = sbl[tx * 5 + 3], bb4 = sbl[tx * 5 + 4];

#pragma unroll
    for (int i = 0; i < 4; i++) {
#pragma unroll
        for (int half = 0; half < 2; half++) {
            int r0 = rowBase + ty * 8 + 2 * i + half;
            float2 q0 = *(float2*)&acc[i][0];
            float2 q1 = *(float2*)&acc[i][1];
            float2 q2 = *(float2*)&acc[i][2];
            float2 q3 = *(float2*)&acc[i][3];
            float2 q4 = *(float2*)&acc[i][4];
            float l0 = (half ? q0.y : q0.x) + bb0;
            float l1 = (half ? q1.y : q1.x) + bb1;
            float l2 = (half ? q2.y : q2.x) + bb2;
            float l3 = (half ? q3.y : q3.x) + bb3;
            float l4 = (half ? q4.y : q4.x) + bb4;

            float m = fmaxf(fmaxf(fmaxf(l0, l1), fmaxf(l2, l3)), l4);
            m = fmaxf(m, __shfl_xor_sync(0xffffffffu, m, 1));
            m = fmaxf(m, __shfl_xor_sync(0xffffffffu, m, 2));
            m = fmaxf(m, __shfl_xor_sync(0xffffffffu, m, 4));
            float se = __expf(l0 - m) + __expf(l1 - m) + __expf(l2 - m)
                     + __expf(l3 - m) + __expf(l4 - m);
            se += __shfl_xor_sync(0xffffffffu, se, 1);
            se += __shfl_xor_sync(0xffffffffu, se, 2);
            se += __shfl_xor_sync(0xffffffffu, se, 4);
            float lse = __logf(se) + m;

            if (r0 < n) {
                float* op = out + (size_t)r0 * C + tx * 5;
                op[0] = l0 - lse; op[1] = l1 - lse; op[2] = l2 - lse;
                op[3] = l3 - lse; op[4] = l4 - lse;
            }
        }
    }
}

// ---------------------------------------------------------------------------
// launch
// ---------------------------------------------------------------------------
extern "C" void kernel_launch(void* const* d_in, const int* in_sizes, int n_in,
                              void* d_out, int out_size) {
    const float* x   = (const float*)d_in[0];
    const int*   ei  = (const int*)d_in[1];
    const float* w0  = (const float*)d_in[2];
    const float* b0  = (const float*)d_in[3];
    const float* w1  = (const float*)d_in[4];
    const float* b1  = (const float*)d_in[5];
    const float* wl  = (const float*)d_in[6];
    const float* bl  = (const float*)d_in[7];
    float* out = (float*)d_out;

    const int n = in_sizes[0] / H;
    const int e = in_sizes[1] / 2;
    const int* src = ei;
    const int* dst = ei + e;

    float *dinv, *lin, *agg, *h0, *csr_w;
    __nv_bfloat16* linb;
    int *cnt, *rowstart, *cursor, *bsum, *csr_src;
    cudaGetSymbolAddress((void**)&dinv,     g_dinv);
    cudaGetSymbolAddress((void**)&cnt,      g_cnt);
    cudaGetSymbolAddress((void**)&rowstart, g_rowstart);
    cudaGetSymbolAddress((void**)&cursor,   g_cursor);
    cudaGetSymbolAddress((void**)&bsum,     g_bsum);
    cudaGetSymbolAddress((void**)&csr_src,  g_csr_src);
    cudaGetSymbolAddress((void**)&csr_w,    g_csr_w);
    cudaGetSymbolAddress((void**)&lin,      g_lin);
    cudaGetSymbolAddress((void**)&linb,     g_linb);
    cudaGetSymbolAddress((void**)&agg,      g_agg);
    cudaGetSymbolAddress((void**)&h0,       g_h0);

    static cudaStream_t s2 = nullptr;
    static cudaEvent_t evFork = nullptr, evJoin = nullptr;
    if (!s2) {
        cudaStreamCreateWithFlags(&s2, cudaStreamNonBlocking);
        cudaEventCreateWithFlags(&evFork, cudaEventDisableTiming);
        cudaEventCreateWithFlags(&evJoin, cudaEventDisableTiming);
    }

    const int TB = 256;
    const int nb = (n + SEG - 1) / SEG;
    const int gemmBlocks   = (n + 63) / 64;
    const int gatherBlocks = (n * 32 + TB - 1) / TB;

    // fork: CSR build on s2, GEMM0 on main stream
    cudaEventRecord(evFork, 0);
    cudaStreamWaitEvent(s2, evFork, 0);

    cudaMemsetAsync(cnt, 0, n * sizeof(int), s2);
    k_count  <<<(e + TB - 1) / TB, TB, 0, s2>>>(dst, cnt, e);
    k_dinv   <<<(n + TB - 1) / TB, TB, 0, s2>>>(cnt, dinv, n);
    k_scan1  <<<nb, SEG, 0, s2>>>(cnt, rowstart, bsum, n);
    k_scan2  <<<1, 256, 0, s2>>>(bsum, rowstart, nb, n);
    k_scan3  <<<(n + TB - 1) / TB, TB, 0, s2>>>(rowstart, bsum, cursor, n);
    k_scatter<<<(e + TB - 1) / TB, TB, 0, s2>>>(src, dst, dinv, cursor,
                                                csr_src, csr_w, e);
    cudaEventRecord(evJoin, s2);

    k_gemm128<<<gemmBlocks, TB>>>(x, w0, lin, linb, n);

    cudaStreamWaitEvent(0, evJoin, 0);

    k_gather <<<gatherBlocks, TB>>>(lin, linb, dinv, rowstart, csr_src, csr_w,
                                    b0, nullptr, h0, n);
    k_gemm128<<<gemmBlocks, TB>>>(h0, w1, lin, linb, n);
    k_gather <<<gatherBlocks, TB>>>(lin, linb, dinv, rowstart, csr_src, csr_w,
                                    b1, h0, agg, n);
    k_cls_gemm<<<(n + 255) / 256, TB>>>(agg, wl, bl, out, n);
}

// round 10
// speedup vs baseline: 1.2318x; 1.1303x over previous
#include <cuda_runtime.h>
#include <cuda_bf16.h>
#include <math.h>

#define NMAX 100000
#define EMAX 1600000
#define H 128
#define C 40
#define SEG 512

typedef unsigned long long ULL;

// ---------------- scratch -------------------------------------------------
__device__ float g_dinv[NMAX];
__device__ int   g_cnt[NMAX];
__device__ int   g_rowstart[NMAX + 1];
__device__ int   g_cursor[NMAX];
__device__ int   g_bsum[(NMAX + SEG - 1) / SEG];
__device__ int   g_csr_src[EMAX];
__device__ float g_csr_w[EMAX];
__device__ float g_lin[(size_t)NMAX * H];
__device__ __nv_bfloat16 g_linb[(size_t)NMAX * H];   // bf16 shadow of lin
__device__ float g_agg[(size_t)NMAX * H];
__device__ float g_h0 [(size_t)NMAX * H];

// ---------------- helpers ---------------------------------------------------
__device__ __forceinline__ ULL ffma2(ULL a, ULL b, ULL c) {
    ULL d;
    asm("fma.rn.f32x2 %0, %1, %2, %3;" : "=l"(d) : "l"(a), "l"(b), "l"(c));
    return d;
}
__device__ __forceinline__ ULL fdup(float x) {
    ULL r;
    asm("mov.b64 %0, {%1, %1};" : "=l"(r) : "f"(x));
    return r;
}
__device__ __forceinline__ unsigned cvt_tf32(float f) {
    unsigned u;
    asm("cvt.rna.tf32.f32 %0, %1;" : "=r"(u) : "f"(f));
    return u;
}
__device__ __forceinline__ ULL policy_evict_last() {
    ULL pol;
    asm("createpolicy.fractional.L2::evict_last.b64 %0, 1.0;" : "=l"(pol));
    return pol;
}
__device__ __forceinline__ ULL policy_evict_first() {
    ULL pol;
    asm("createpolicy.fractional.L2::evict_first.b64 %0, 1.0;" : "=l"(pol));
    return pol;
}
__device__ __forceinline__ ULL ld_linb(const void* p, ULL pol) {
    ULL v;
    asm("ld.global.nc.L2::cache_hint.b64 %0, [%1], %2;"
        : "=l"(v) : "l"(p), "l"(pol));
    return v;
}
__device__ __forceinline__ void st_linb32(void* p, unsigned v, ULL pol) {
    asm volatile("st.global.L2::cache_hint.b32 [%0], %1, %2;"
                 :: "l"(p), "r"(v), "l"(pol) : "memory");
}
__device__ __forceinline__ float4 ld_stream_f4(const void* p, ULL pol) {
    float4 v;
    asm("ld.global.nc.L2::cache_hint.v4.f32 {%0,%1,%2,%3}, [%4], %5;"
        : "=f"(v.x), "=f"(v.y), "=f"(v.z), "=f"(v.w) : "l"(p), "l"(pol));
    return v;
}
__device__ __forceinline__ void st_stream_f4(void* p, float4 v, ULL pol) {
    asm volatile("st.global.L2::cache_hint.v4.f32 [%0], {%1,%2,%3,%4}, %5;"
                 :: "l"(p), "f"(v.x), "f"(v.y), "f"(v.z), "f"(v.w), "l"(pol)
                 : "memory");
}
__device__ __forceinline__ void st_stream_f2(void* p, float2 v, ULL pol) {
    asm volatile("st.global.L2::cache_hint.v2.f32 [%0], {%1,%2}, %3;"
                 :: "l"(p), "f"(v.x), "f"(v.y), "l"(pol) : "memory");
}

// ---------------- CSR build ------------------------------------------------
__global__ void k_count(const int* __restrict__ dst, int* cnt, int e) {
    int i = blockIdx.x * blockDim.x + threadIdx.x;
    if (i < e) atomicAdd(&cnt[dst[i]], 1);
}
__global__ void k_dinv(const int* __restrict__ cnt, float* dinv, int n) {
    int i = blockIdx.x * blockDim.x + threadIdx.x;
    if (i < n) dinv[i] = rsqrtf((float)(cnt[i] + 1));
}
__global__ void k_scan1(const int* __restrict__ cnt, int* rowstart, int* bsum, int n) {
    __shared__ int sh[SEG];
    int i = blockIdx.x * SEG + threadIdx.x;
    int v = (i < n) ? cnt[i] : 0;
    sh[threadIdx.x] = v;
    __syncthreads();
#pragma unroll
    for (int o = 1; o < SEG; o <<= 1) {
        int t = (threadIdx.x >= o) ? sh[threadIdx.x - o] : 0;
        __syncthreads();
        sh[threadIdx.x] += t;
        __syncthreads();
    }
    if (i < n) rowstart[i] = sh[threadIdx.x] - v;
    if (threadIdx.x == SEG - 1) bsum[blockIdx.x] = sh[SEG - 1];
}
__global__ void k_scan2(int* bsum, int* rowstart, int nb, int n) {
    __shared__ int sh[256];
    int v = (threadIdx.x < nb) ? bsum[threadIdx.x] : 0;
    sh[threadIdx.x] = v;
    __syncthreads();
#pragma unroll
    for (int o = 1; o < 256; o <<= 1) {
        int t = (threadIdx.x >= o) ? sh[threadIdx.x - o] : 0;
        __syncthreads();
        sh[threadIdx.x] += t;
        __syncthreads();
    }
    if (threadIdx.x < nb) bsum[threadIdx.x] = sh[threadIdx.x] - v;
    if (threadIdx.x == 255) rowstart[n] = sh[255];
}
__global__ void k_scan3(int* rowstart, const int* __restrict__ bsum, int* cursor, int n) {
    int i = blockIdx.x * blockDim.x + threadIdx.x;
    if (i < n) {
        int r = rowstart[i] + bsum[i / SEG];
        rowstart[i] = r;
        cursor[i]   = r;
    }
}
__global__ void k_scatter(const int* __restrict__ src, const int* __restrict__ dst,
                          const float* __restrict__ dinv, int* cursor,
                          int* csr_src, float* csr_w, int e) {
    int i = blockIdx.x * blockDim.x + threadIdx.x;
    if (i >= e) return;
    int s = src[i], d = dst[i];
    int p = atomicAdd(&cursor[d], 1);
    csr_src[p] = s;
    csr_w[p]   = dinv[s] * dinv[d];
}

// ---------------------------------------------------------------------------
// tf32 tensor-core GEMM: C[M,128] = A[M,128] @ B[128,128]
// BM=128 BN=128 BK=32, 256 threads (8 warps, warp tile 32x64), mma.m16n8k8
// smem stride 136 (==8 mod 32) => conflict-free fragment LDS
// emits fp32 C (evict_first) and bf16 shadow (evict_last)
// ---------------------------------------------------------------------------
__global__ void __launch_bounds__(256)
k_gemm_tf32(const float* __restrict__ A,
            const float* __restrict__ B,
            float* __restrict__ Cm,
            __nv_bfloat16* __restrict__ Cb, int M) {
    __shared__ unsigned AsT[32][136];   // [k][m]
    __shared__ unsigned Bs [32][136];   // [k][n]

    const int tid  = threadIdx.x;
    const int lane = tid & 31;
    const int wid  = tid >> 5;
    const int warp_m = wid & 3;
    const int warp_n = wid >> 2;
    const int rowBase = blockIdx.x * 128;

    const int r = lane >> 2;
    const int t = lane & 3;

    float acc[2][8][4];
#pragma unroll
    for (int i = 0; i < 2; i++)
#pragma unroll
        for (int j = 0; j < 8; j++)
#pragma unroll
            for (int q = 0; q < 4; q++) acc[i][j][q] = 0.0f;

    for (int k0 = 0; k0 < 128; k0 += 32) {
#pragma unroll
        for (int it = 0; it < 4; it++) {
            int idx = tid + it * 256;
            int m   = idx & 127;
            int kq  = idx >> 7;
            int gr  = rowBase + m;
            float4 v = make_float4(0.f, 0.f, 0.f, 0.f);
            if (gr < M) v = *(const float4*)(A + (size_t)gr * 128 + k0 + kq * 4);
            AsT[kq * 4 + 0][m] = cvt_tf32(v.x);
            AsT[kq * 4 + 1][m] = cvt_tf32(v.y);
            AsT[kq * 4 + 2][m] = cvt_tf32(v.z);
            AsT[kq * 4 + 3][m] = cvt_tf32(v.w);
        }
#pragma unroll
        for (int it = 0; it < 4; it++) {
            int idx = tid + it * 256;
            int k   = idx >> 5;
            int n4  = (idx & 31) << 2;
            float4 v = *(const float4*)(B + (size_t)(k0 + k) * 128 + n4);
            uint4 u = make_uint4(cvt_tf32(v.x), cvt_tf32(v.y),
                                 cvt_tf32(v.z), cvt_tf32(v.w));
            *(uint4*)&Bs[k][n4] = u;
        }
        __syncthreads();

#pragma unroll
        for (int ks = 0; ks < 4; ks++) {
            const int kb = ks * 8;
            unsigned a[2][4];
#pragma unroll
            for (int fm = 0; fm < 2; fm++) {
                int mb = warp_m * 32 + fm * 16;
                a[fm][0] = AsT[kb + t    ][mb + r];
                a[fm][1] = AsT[kb + t    ][mb + r + 8];
                a[fm][2] = AsT[kb + t + 4][mb + r];
                a[fm][3] = AsT[kb + t + 4][mb + r + 8];
            }
#pragma unroll
            for (int fn = 0; fn < 8; fn++) {
                int nb = warp_n * 64 + fn * 8;
                unsigned b0 = Bs[kb + t    ][nb + r];
                unsigned b1 = Bs[kb + t + 4][nb + r];
#pragma unroll
                for (int fm = 0; fm < 2; fm++) {
                    asm("mma.sync.aligned.m16n8k8.row.col.f32.tf32.tf32.f32 "
                        "{%0,%1,%2,%3}, {%4,%5,%6,%7}, {%8,%9}, {%0,%1,%2,%3};"
                        : "+f"(acc[fm][fn][0]), "+f"(acc[fm][fn][1]),
                          "+f"(acc[fm][fn][2]), "+f"(acc[fm][fn][3])
                        : "r"(a[fm][0]), "r"(a[fm][1]), "r"(a[fm][2]), "r"(a[fm][3]),
                          "r"(b0), "r"(b1));
                }
            }
        }
        __syncthreads();
    }

    const ULL polLast  = policy_evict_last();
    const ULL polFirst = policy_evict_first();

#pragma unroll
    for (int fm = 0; fm < 2; fm++) {
        int r0 = rowBase + warp_m * 32 + fm * 16 + r;
        int r1 = r0 + 8;
#pragma unroll
        for (int fn = 0; fn < 8; fn++) {
            int col = warp_n * 64 + fn * 8 + 2 * t;
            if (r0 < M) {
                float2 v = make_float2(acc[fm][fn][0], acc[fm][fn][1]);
                st_stream_f2(Cm + (size_t)r0 * 128 + col, v, polFirst);
                __nv_bfloat162 h = __float22bfloat162_rn(v);
                st_linb32(Cb + (size_t)r0 * 128 + col, *(unsigned*)&h, polLast);
            }
            if (r1 < M) {
                float2 v = make_float2(acc[fm][fn][2], acc[fm][fn][3]);
                st_stream_f2(Cm + (size_t)r1 * 128 + col, v, polFirst);
                __nv_bfloat162 h = __float22bfloat162_rn(v);
                st_linb32(Cb + (size_t)r1 * 128 + col, *(unsigned*)&h, polLast);
            }
        }
    }
}

// ---------------------------------------------------------------------------
// fused gather (warp per dst node, unroll 4) — unchanged from R9
// ---------------------------------------------------------------------------
__device__ __forceinline__ void acc_bf16(float4& acc, float w, ULL packed) {
    __nv_bfloat162 lo = *(__nv_bfloat162*)&packed;
    __nv_bfloat162 hi = *((__nv_bfloat162*)&packed + 1);
    float2 f0 = __bfloat1622float2(lo);
    float2 f1 = __bfloat1622float2(hi);
    acc.x = fmaf(w, f0.x, acc.x);
    acc.y = fmaf(w, f0.y, acc.y);
    acc.z = fmaf(w, f1.x, acc.z);
    acc.w = fmaf(w, f1.y, acc.w);
}

__global__ void k_gather(const float* __restrict__ lin,
                         const __nv_bfloat16* __restrict__ linb,
                         const float* __restrict__ dinv,
                         const int* __restrict__ rowstart,
                         const int* __restrict__ csr_src,
                         const float* __restrict__ csr_w,
                         const float* __restrict__ bias,
                         const float* __restrict__ res,
                         float* __restrict__ out, int n) {
    int v = (blockIdx.x * blockDim.x + threadIdx.x) >> 5;
    int lane = threadIdx.x & 31;
    if (v >= n) return;

    const ULL polLast  = policy_evict_last();
    const ULL polFirst = policy_evict_first();

    int beg = rowstart[v];
    int end = rowstart[v + 1];
    float dv = dinv[v];
    float sl = dv * dv;
    const size_t lo = (size_t)(lane << 2);

    float4 acc = ld_stream_f4(lin + (size_t)v * 128 + lo, polFirst);
    acc.x *= sl; acc.y *= sl; acc.z *= sl; acc.w *= sl;

    int i = beg;
    for (; i + 3 < end; i += 4) {
        int   s0 = csr_src[i],     s1 = csr_src[i + 1];
        int   s2 = csr_src[i + 2], s3 = csr_src[i + 3];
        float w0 = csr_w[i],       w1 = csr_w[i + 1];
        float w2 = csr_w[i + 2],   w3 = csr_w[i + 3];
        ULL x0 = ld_linb(linb + (size_t)s0 * 128 + lo, polLast);
        ULL x1 = ld_linb(linb + (size_t)s1 * 128 + lo, polLast);
        ULL x2 = ld_linb(linb + (size_t)s2 * 128 + lo, polLast);
        ULL x3 = ld_linb(linb + (size_t)s3 * 128 + lo, polLast);
        acc_bf16(acc, w0, x0);
        acc_bf16(acc, w1, x1);
        acc_bf16(acc, w2, x2);
        acc_bf16(acc, w3, x3);
    }
    for (; i < end; i++) {
        int   s0 = csr_src[i];
        float w0 = csr_w[i];
        ULL x0 = ld_linb(linb + (size_t)s0 * 128 + lo, polLast);
        acc_bf16(acc, w0, x0);
    }

    float4 bb = ((const float4*)bias)[lane];
    acc.x = fmaxf(acc.x + bb.x, 0.f);
    acc.y = fmaxf(acc.y + bb.y, 0.f);
    acc.z = fmaxf(acc.z + bb.z, 0.f);
    acc.w = fmaxf(acc.w + bb.w, 0.f);
    if (res) {
        float4 rr = ld_stream_f4(res + (size_t)v * 128 + lo, polFirst);
        acc.x += rr.x; acc.y += rr.y; acc.z += rr.z; acc.w += rr.w;
    }
    st_stream_f4(out + (size_t)v * 128 + lo, acc, polFirst);
}

// ---------------------------------------------------------------------------
// classifier GEMM + fused log_softmax (packed f32x2) — unchanged from R9
// ---------------------------------------------------------------------------
__global__ void k_cls_gemm(const float* __restrict__ h,
                           const float* __restrict__ wl,
                           const float* __restrict__ bl,
                           float* __restrict__ out, int n) {
    __shared__ float AsT[16][258];
    __shared__ float Bsf[16 * C];
    __shared__ float sbl[C];

    const int tx = threadIdx.x & 7;
    const int ty = threadIdx.x >> 3;
    const int rowBase = blockIdx.x * 256;

    if (threadIdx.x < C) sbl[threadIdx.x] = bl[threadIdx.x];

    ULL acc[4][5];
#pragma unroll
    for (int i = 0; i < 4; i++)
#pragma unroll
        for (int j = 0; j < 5; j++) acc[i][j] = 0ull;

    const int gr = rowBase + threadIdx.x;

    for (int k0 = 0; k0 < 128; k0 += 16) {
#pragma unroll
        for (int i = 0; i < 4; i++) {
            float4 v = make_float4(0.f, 0.f, 0.f, 0.f);
            if (gr < n) v = *(const float4*)(h + (size_t)gr * 128 + k0 + i * 4);
            AsT[i * 4 + 0][threadIdx.x] = v.x;
            AsT[i * 4 + 1][threadIdx.x] = v.y;
            AsT[i * 4 + 2][threadIdx.x] = v.z;
            AsT[i * 4 + 3][threadIdx.x] = v.w;
        }
        for (int i = threadIdx.x; i < 16 * C; i += 256)
            Bsf[i] = wl[k0 * C + i];
        __syncthreads();

#pragma unroll 4
        for (int kk = 0; kk < 16; kk++) {
            ULL a0 = *(const ULL*)&AsT[kk][ty * 8 + 0];
            ULL a1 = *(const ULL*)&AsT[kk][ty * 8 + 2];
            ULL a2 = *(const ULL*)&AsT[kk][ty * 8 + 4];
            ULL a3 = *(const ULL*)&AsT[kk][ty * 8 + 6];
            const float* bp = &Bsf[kk * C + tx * 5];
            ULL b0 = fdup(bp[0]), b1 = fdup(bp[1]), b2 = fdup(bp[2]);
            ULL b3 = fdup(bp[3]), b4 = fdup(bp[4]);
#define CLS_ROW(i, ai) \
            acc[i][0] = ffma2(ai, b0, acc[i][0]); \
            acc[i][1] = ffma2(ai, b1, acc[i][1]); \
            acc[i][2] = ffma2(ai, b2, acc[i][2]); \
            acc[i][3] = ffma2(ai, b3, acc[i][3]); \
            acc[i][4] = ffma2(ai, b4, acc[i][4]);
            CLS_ROW(0, a0) CLS_ROW(1, a1) CLS_ROW(2, a2) CLS_ROW(3, a3)
#undef CLS_ROW
        }
        __syncthreads();
    }

    const float bb0 = sbl[tx * 5 + 0], bb1 = sbl[tx * 5 + 1], bb2 = sbl[tx * 5 + 2];
    const float bb3 = sbl[tx * 5 + 3], bb4 = sbl[tx * 5 + 4];

#pragma unroll
    for (int i = 0; i < 4; i++) {
#pragma unroll
        for (int half = 0; half < 2; half++) {
            int r0 = rowBase + ty * 8 + 2 * i + half;
            float2 q0 = *(float2*)&acc[i][0];
            float2 q1 = *(float2*)&acc[i][1];
            float2 q2 = *(float2*)&acc[i][2];
            float2 q3 = *(float2*)&acc[i][3];
            float2 q4 = *(float2*)&acc[i][4];
            float l0 = (half ? q0.y : q0.x) + bb0;
            float l1 = (half ? q1.y : q1.x) + bb1;
            float l2 = (half ? q2.y : q2.x) + bb2;
            float l3 = (half ? q3.y : q3.x) + bb3;
            float l4 = (half ? q4.y : q4.x) + bb4;

            float m = fmaxf(fmaxf(fmaxf(l0, l1), fmaxf(l2, l3)), l4);
            m = fmaxf(m, __shfl_xor_sync(0xffffffffu, m, 1));
            m = fmaxf(m, __shfl_xor_sync(0xffffffffu, m, 2));
            m = fmaxf(m, __shfl_xor_sync(0xffffffffu, m, 4));
            float se = __expf(l0 - m) + __expf(l1 - m) + __expf(l2 - m)
                     + __expf(l3 - m) + __expf(l4 - m);
            se += __shfl_xor_sync(0xffffffffu, se, 1);
            se += __shfl_xor_sync(0xffffffffu, se, 2);
            se += __shfl_xor_sync(0xffffffffu, se, 4);
            float lse = __logf(se) + m;

            if (r0 < n) {
                float* op = out + (size_t)r0 * C + tx * 5;
                op[0] = l0 - lse; op[1] = l1 - lse; op[2] = l2 - lse;
                op[3] = l3 - lse; op[4] = l4 - lse;
            }
        }
    }
}

// ---------------------------------------------------------------------------
// launch
// ---------------------------------------------------------------------------
extern "C" void kernel_launch(void* const* d_in, const int* in_sizes, int n_in,
                              void* d_out, int out_size) {
    const float* x   = (const float*)d_in[0];
    const int*   ei  = (const int*)d_in[1];
    const float* w0  = (const float*)d_in[2];
    const float* b0  = (const float*)d_in[3];
    const float* w1  = (const float*)d_in[4];
    const float* b1  = (const float*)d_in[5];
    const float* wl  = (const float*)d_in[6];
    const float* bl  = (const float*)d_in[7];
    float* out = (float*)d_out;

    const int n = in_sizes[0] / H;
    const int e = in_sizes[1] / 2;
    const int* src = ei;
    const int* dst = ei + e;

    float *dinv, *lin, *agg, *h0, *csr_w;
    __nv_bfloat16* linb;
    int *cnt, *rowstart, *cursor, *bsum, *csr_src;
    cudaGetSymbolAddress((void**)&dinv,     g_dinv);
    cudaGetSymbolAddress((void**)&cnt,      g_cnt);
    cudaGetSymbolAddress((void**)&rowstart, g_rowstart);
    cudaGetSymbolAddress((void**)&cursor,   g_cursor);
    cudaGetSymbolAddress((void**)&bsum,     g_bsum);
    cudaGetSymbolAddress((void**)&csr_src,  g_csr_src);
    cudaGetSymbolAddress((void**)&csr_w,    g_csr_w);
    cudaGetSymbolAddress((void**)&lin,      g_lin);
    cudaGetSymbolAddress((void**)&linb,     g_linb);
    cudaGetSymbolAddress((void**)&agg,      g_agg);
    cudaGetSymbolAddress((void**)&h0,       g_h0);

    static cudaStream_t s2 = nullptr;
    static cudaEvent_t evFork = nullptr, evJoin = nullptr;
    if (!s2) {
        cudaStreamCreateWithFlags(&s2, cudaStreamNonBlocking);
        cudaEventCreateWithFlags(&evFork, cudaEventDisableTiming);
        cudaEventCreateWithFlags(&evJoin, cudaEventDisableTiming);
    }

    const int TB = 256;
    const int nb = (n + SEG - 1) / SEG;
    const int gemmBlocks   = (n + 127) / 128;
    const int gatherBlocks = (n * 32 + TB - 1) / TB;

    // fork: CSR build on s2, GEMM0 on main stream
    cudaEventRecord(evFork, 0);
    cudaStreamWaitEvent(s2, evFork, 0);

    cudaMemsetAsync(cnt, 0, n * sizeof(int), s2);
    k_count  <<<(e + TB - 1) / TB, TB, 0, s2>>>(dst, cnt, e);
    k_dinv   <<<(n + TB - 1) / TB, TB, 0, s2>>>(cnt, dinv, n);
    k_scan1  <<<nb, SEG, 0, s2>>>(cnt, rowstart, bsum, n);
    k_scan2  <<<1, 256, 0, s2>>>(bsum, rowstart, nb, n);
    k_scan3  <<<(n + TB - 1) / TB, TB, 0, s2>>>(rowstart, bsum, cursor, n);
    k_scatter<<<(e + TB - 1) / TB, TB, 0, s2>>>(src, dst, dinv, cursor,
                                                csr_src, csr_w, e);
    cudaEventRecord(evJoin, s2);

    k_gemm_tf32<<<gemmBlocks, TB>>>(x, w0, lin, linb, n);

    cudaStreamWaitEvent(0, evJoin, 0);

    k_gather <<<gatherBlocks, TB>>>(lin, linb, dinv, rowstart, csr_src, csr_w,
                                    b0, nullptr, h0, n);
    k_gemm_tf32<<<gemmBlocks, TB>>>(h0, w1, lin, linb, n);
    k_gather <<<gatherBlocks, TB>>>(lin, linb, dinv, rowstart, csr_src, csr_w,
                                    b1, h0, agg, n);
    k_cls_gemm<<<(n + 255) / 256, TB>>>(agg, wl, bl, out, n);
}